// round 11
// baseline (speedup 1.0000x reference)
#include <cuda_runtime.h>

#define NB      2
#define NPTS    8192
#define NDIM    64
#define KSEL    16
#define QB      32
#define CB      128
#define THREADS 256

// Precomputed squared norms (allocation-free scratch).
__device__ float g_sq[NB * NPTS];

// lexicographic (distance, index) ascending — stable top_k tie order
__device__ __forceinline__ bool keyless(float d1, int i1, float d2, int i2) {
    return (d1 < d2) || (d1 == d2 && i1 < i2);
}

// Serial insert into a shared sorted-16 list (executed by lane 0 only).
// Re-checks against the LIVE 16th entry, so stale screening thresholds are safe.
__device__ __forceinline__ void sins16(float* tl_d, int* tl_i, float dv, int idx) {
    if (keyless(dv, idx, tl_d[KSEL - 1], tl_i[KSEL - 1])) {
        int p = KSEL - 1;
        while (p > 0 && keyless(dv, idx, tl_d[p - 1], tl_i[p - 1])) {
            tl_d[p] = tl_d[p - 1];
            tl_i[p] = tl_i[p - 1];
            p--;
        }
        tl_d[p] = dv;
        tl_i[p] = idx;
    }
}

// ---------------------------------------------------------------------------
// Kernel 1: ||x||^2 per point — SAME sequential fma chain (c=0..63) as the
// dot products below, so the self-distance cancels to exactly 0 in fp32.
// ---------------------------------------------------------------------------
__global__ void norms_kernel(const float* __restrict__ x) {
    int p = blockIdx.x * blockDim.x + threadIdx.x;
    if (p >= NB * NPTS) return;
    int b = p >> 13;
    int n = p & (NPTS - 1);
    const float* xb = x + b * (NDIM * NPTS);
    float acc = 0.0f;
#pragma unroll
    for (int c = 0; c < NDIM; c++) {
        float v = xb[c * NPTS + n];
        acc = fmaf(v, v, acc);
    }
    g_sq[p] = acc;
}

// ---------------------------------------------------------------------------
// Kernel 2: fused Gram + warp-cooperative top-16 with one-shot screening.
//   grid (NPTS/QB, NB), 256 threads (8 warps). Block: 32 queries; 64 tiles of
//   128 candidates. Thread (qg, cg): queries {2qg,2qg+1} x candidates
//   {4cg..4cg+3, 64+4cg..+3}. ONE sorted top-16 per query in smem, owned by
//   its warp. Per tile: ONE register-threshold ballot per sub; the per-j
//   insert machinery runs only when the ballot is nonzero (rare).
// ---------------------------------------------------------------------------
__global__ __launch_bounds__(THREADS) void knn_kernel(const float* __restrict__ x,
                                                      float* __restrict__ out) {
    __shared__ __align__(16) float qs[NDIM * QB];   //  8 KB  [k][q]
    __shared__ __align__(16) float cs[NDIM * CB];   // 32 KB  [k][p]
    __shared__ float cssq[CB];
    __shared__ float qsq[QB];
    __shared__ float tld[QB * KSEL];                // sorted dists per query
    __shared__ int   tli[QB * KSEL];                // indices

    const int tid    = threadIdx.x;
    const int b      = blockIdx.y;
    const int n_base = blockIdx.x * QB;
    const float* xb  = x + b * (NDIM * NPTS);
    const float* sqb = g_sq + b * NPTS;

    for (int i = tid; i < NDIM * QB; i += THREADS) {
        int q = i & (QB - 1);
        int k = i >> 5;
        qs[k * QB + q] = xb[k * NPTS + n_base + q];
    }
    if (tid < QB) qsq[tid] = sqb[n_base + tid];
    for (int i = tid; i < QB * KSEL; i += THREADS) {
        tld[i] = __int_as_float(0x7f800000);   // +inf
        tli[i] = 0x7fffffff;
    }
    __syncthreads();

    const int lane = tid & 31;
    const int warp = tid >> 5;
    const int qg   = tid >> 4;          // 0..15
    const int cg   = tid & 15;          // 0..15
    const float sq0 = qsq[2 * qg];
    const float sq1 = qsq[2 * qg + 1];

    // Lane's query for each sub: sub=0 -> d0 (q_lo / q_lo+2), sub=1 -> d1.
    const int myq0 = 4 * warp + 0 + ((lane >> 4) << 1);
    const int myq1 = 4 * warp + 1 + ((lane >> 4) << 1);

    const float2* qs2 = reinterpret_cast<const float2*>(qs);
    const float4* csr = reinterpret_cast<const float4*>(cs);
    float4*       csw = reinterpret_cast<float4*>(cs);
    const float4* x4  = reinterpret_cast<const float4*>(xb);

    for (int base = 0; base < NPTS; base += CB) {
        __syncthreads();   // previous tile fully consumed

        for (int i = tid; i < NDIM * (CB / 4); i += THREADS) {
            int p4 = i & 31;
            int c  = i >> 5;
            csw[c * (CB / 4) + p4] = x4[(c * NPTS + base) / 4 + p4];
        }
        if (tid < CB) cssq[tid] = sqb[base + tid];
        __syncthreads();

        // --- Gram micro-tile: 2 queries x 8 candidates ---
        float acc0[8], acc1[8];
#pragma unroll
        for (int j = 0; j < 8; j++) { acc0[j] = 0.0f; acc1[j] = 0.0f; }

#pragma unroll 8
        for (int k = 0; k < NDIM; k++) {
            float2 a  = qs2[k * (QB / 2) + qg];          // broadcast
            float4 mA = csr[k * (CB / 4) + cg];          // cands 4cg..4cg+3
            float4 mB = csr[k * (CB / 4) + 16 + cg];     // cands 64+4cg..+3
            acc0[0] = fmaf(a.x, mA.x, acc0[0]);
            acc0[1] = fmaf(a.x, mA.y, acc0[1]);
            acc0[2] = fmaf(a.x, mA.z, acc0[2]);
            acc0[3] = fmaf(a.x, mA.w, acc0[3]);
            acc0[4] = fmaf(a.x, mB.x, acc0[4]);
            acc0[5] = fmaf(a.x, mB.y, acc0[5]);
            acc0[6] = fmaf(a.x, mB.z, acc0[6]);
            acc0[7] = fmaf(a.x, mB.w, acc0[7]);
            acc1[0] = fmaf(a.y, mA.x, acc1[0]);
            acc1[1] = fmaf(a.y, mA.y, acc1[1]);
            acc1[2] = fmaf(a.y, mA.z, acc1[2]);
            acc1[3] = fmaf(a.y, mA.w, acc1[3]);
            acc1[4] = fmaf(a.y, mB.x, acc1[4]);
            acc1[5] = fmaf(a.y, mB.y, acc1[5]);
            acc1[6] = fmaf(a.y, mB.z, acc1[6]);
            acc1[7] = fmaf(a.y, mB.w, acc1[7]);
        }

        // Distance epilogue (registers).
        float d0[8], d1[8];
#pragma unroll
        for (int j = 0; j < 8; j++) {
            int c = (j < 4) ? (4 * cg + j) : (64 + 4 * cg + (j - 4));
            float sc = cssq[c];
            d0[j] = (sq0 + (-2.0f * acc0[j])) + sc;
            d1[j] = (sq1 + (-2.0f * acc1[j])) + sc;
        }

        // --- Selection: one-shot screen per sub, slow path only if needed ---
#pragma unroll
        for (int sub = 0; sub < 2; sub++) {
            const int q_lo = 4 * warp + sub;
            const int q_hi = q_lo + 2;
            const int myq  = (sub == 0) ? myq0 : myq1;

            // Register threshold (possibly stale after other sub's inserts —
            // safe: passes are a superset; sins16 re-checks live list).
            float thr  = tld[myq * KSEL + KSEL - 1];
            int   thri = tli[myq * KSEL + KSEL - 1];

            bool any = false;
#pragma unroll
            for (int j = 0; j < 8; j++) {
                float d = (sub == 0) ? d0[j] : d1[j];
                int   c = (j < 4) ? (4 * cg + j) : (64 + 4 * cg + (j - 4));
                any |= keyless(d, base + c, thr, thri);
            }

            unsigned scr = __ballot_sync(0xffffffffu, any);
            if (scr != 0u) {
                // Slow path: per-j ballots + serial inserts by lane 0.
#pragma unroll
                for (int j = 0; j < 8; j++) {
                    float d   = (sub == 0) ? d0[j] : d1[j];
                    int   cme = (j < 4) ? (4 * cg + j) : (64 + 4 * cg + (j - 4));
                    float lt  = tld[myq * KSEL + KSEL - 1];
                    int   lti = tli[myq * KSEL + KSEL - 1];
                    bool pass = keyless(d, base + cme, lt, lti);
                    unsigned bal = __ballot_sync(0xffffffffu, pass);
                    if (bal) {
                        unsigned lom = bal & 0xffffu;
                        while (lom) {
                            int src = __ffs(lom) - 1;
                            lom &= lom - 1;
                            float dv = __shfl_sync(0xffffffffu, d, src);
                            if (lane == 0) {
                                int c = (j < 4) ? (4 * src + j) : (64 + 4 * src + (j - 4));
                                sins16(tld + q_lo * KSEL, tli + q_lo * KSEL, dv, base + c);
                            }
                        }
                        unsigned him = bal >> 16;
                        while (him) {
                            int s = __ffs(him) - 1;
                            him &= him - 1;
                            float dv = __shfl_sync(0xffffffffu, d, s + 16);
                            if (lane == 0) {
                                int c = (j < 4) ? (4 * s + j) : (64 + 4 * s + (j - 4));
                                sins16(tld + q_hi * KSEL, tli + q_hi * KSEL, dv, base + c);
                            }
                        }
                        __syncwarp();
                    }
                }
            }
        }
    }

    // Output (2, NB, NPTS, KSEL), float32 values.
    __syncthreads();
    for (int i = tid; i < QB * KSEL; i += THREADS) {
        int q = i >> 4;
        int k = i & (KSEL - 1);
        int n = n_base + q;
        int base0 = (b * NPTS + n) * KSEL + k;            // plane 0: nn_idx
        int base1 = NB * NPTS * KSEL + base0;             // plane 1: center_idx
        out[base0] = (float)tli[q * KSEL + k];
        out[base1] = (float)n;
    }
}

extern "C" void kernel_launch(void* const* d_in, const int* in_sizes, int n_in,
                              void* d_out, int out_size) {
    const float* x = (const float*)d_in[0];
    float* out = (float*)d_out;
    norms_kernel<<<(NB * NPTS + THREADS - 1) / THREADS, THREADS>>>(x);
    knn_kernel<<<dim3(NPTS / QB, NB), THREADS>>>(x, out);
}